// round 13
// baseline (speedup 1.0000x reference)
#include <cuda_runtime.h>
#include <cuda_fp16.h>
#include <cstddef>
#include <cstdint>

#define BATCH 4
#define SEQ   4096
#define DIM   1024
#define QKD   256
#define MTOT  16384

// CTA 128x128, warp tile 32x64, 8 warps, BK=64, 2 stages
#define BM 128
#define BN 128
#define BK 64
#define NSTAGE 2
#define PA  72     // A smem pitch (halfs), 144B rows -> conflict-free ldmatrix
#define PB  72     // B TN pitch
#define PBN 136    // B NN pitch (64 rows x 128 cols)
#define ASZ (BM*PA)            // 9216 halfs
#define BSZ (BM*PB)            // 9216 halfs (>= 64*136 = 8704)
#define STGH (ASZ+BSZ)         // halfs per stage
#define SMEM_DYN (NSTAGE*STGH*2)   // 73728 B

// ---------------- scratch (bss device globals; allocation-free) ----------------
__device__ __half g_hq [(size_t)MTOT*DIM];
__device__ __half g_hk [(size_t)MTOT*DIM];
__device__ __half g_hv [(size_t)MTOT*DIM];
__device__ __half g_hWq[(size_t)QKD*DIM];
__device__ __half g_hWk[(size_t)QKD*DIM];
__device__ __half g_hWv[(size_t)DIM*DIM];
__device__ __half g_qp [(size_t)MTOT*QKD];
__device__ __half g_kp [(size_t)MTOT*QKD];
__device__ __half g_vp [(size_t)MTOT*DIM];
__device__ __half g_z  [(size_t)BATCH*SEQ*SEQ];

// ---------------- helpers ----------------
__device__ __forceinline__ uint32_t s2u(const void* p) {
    return (uint32_t)__cvta_generic_to_shared(p);
}
__device__ __forceinline__ void cpa16(uint32_t dst, const void* src) {
    asm volatile("cp.async.cg.shared.global [%0], [%1], 16;" :: "r"(dst), "l"(src));
}
__device__ __forceinline__ void ldsm4(uint32_t* r, uint32_t a) {
    asm volatile("ldmatrix.sync.aligned.m8n8.x4.shared.b16 {%0,%1,%2,%3}, [%4];"
        : "=r"(r[0]), "=r"(r[1]), "=r"(r[2]), "=r"(r[3]) : "r"(a));
}
__device__ __forceinline__ void ldsm4t(uint32_t* r, uint32_t a) {
    asm volatile("ldmatrix.sync.aligned.m8n8.x4.trans.shared.b16 {%0,%1,%2,%3}, [%4];"
        : "=r"(r[0]), "=r"(r[1]), "=r"(r[2]), "=r"(r[3]) : "r"(a));
}
__device__ __forceinline__ void mma16816(float* d, const uint32_t* a, const uint32_t* b) {
    asm volatile(
        "mma.sync.aligned.m16n8k16.row.col.f32.f16.f16.f32 "
        "{%0,%1,%2,%3}, {%4,%5,%6,%7}, {%8,%9}, {%0,%1,%2,%3};"
        : "+f"(d[0]), "+f"(d[1]), "+f"(d[2]), "+f"(d[3])
        : "r"(a[0]), "r"(a[1]), "r"(a[2]), "r"(a[3]), "r"(b[0]), "r"(b[1]));
}
// sigmoid(x) = 0.5*tanh(0.5*x) + 0.5  via HW MUFU.TANH (1 MUFU, no divide)
__device__ __forceinline__ float fast_sigmoid(float x) {
    float t;
    asm("tanh.approx.f32 %0, %1;" : "=f"(t) : "f"(x * 0.5f));
    return fmaf(t, 0.5f, 0.5f);
}

// ---------------- fp32 -> fp16 convert (grid.y selects segment) ----------------
struct PPArgs {
    const float* src[2];
    __half* dst[2];
    size_t n4[2];
};
__global__ void cvt_half_k(PPArgs pp) {
    const int seg = blockIdx.y;
    const float* in = pp.src[seg];
    __half2* out = reinterpret_cast<__half2*>(pp.dst[seg]);
    const size_t n4 = pp.n4[seg];
    size_t i = (size_t)blockIdx.x * blockDim.x + threadIdx.x;
    const size_t stride = (size_t)gridDim.x * blockDim.x;
    for (; i < n4; i += stride) {
        float4 v = reinterpret_cast<const float4*>(in)[i];
        out[2 * i]     = __floats2half2_rn(v.x, v.y);
        out[2 * i + 1] = __floats2half2_rn(v.z, v.w);
    }
}

// ---------------- fp16 tensor-core GEMM ----------------
// C[m][n] = sum_k A[m][k] * B_frag(n,k); blockIdx.z batches via element strides
//   BNN=false: B gmem is [N][K] (K-contig)  -> ldmatrix non-trans
//   BNN=true : B gmem is [K][N] (N-contig)  -> ldmatrix.trans
#define EPI_BIAS 0
#define EPI_SIG  1
#define EPI_NONE 2

template<int EPI, bool BNN, typename OutT>
__global__ __launch_bounds__(256, 2)
void hgemm(const __half* __restrict__ A, const __half* __restrict__ B,
           const float* __restrict__ bias, OutT* __restrict__ C,
           int K, size_t lda, size_t ldb, size_t ldc,
           size_t sA, size_t sB, size_t sC, size_t sBias, float scale)
{
    extern __shared__ __align__(128) __half smem[];

    const int b = blockIdx.z;
    A += (size_t)b * sA;  B += (size_t)b * sB;  C += (size_t)b * sC;
    if (EPI == EPI_BIAS) bias += (size_t)b * sBias;
    const int m0 = blockIdx.y * BM;
    const int n0 = blockIdx.x * BN;
    const int tid  = threadIdx.x;
    const int lane = tid & 31;
    const int warp = tid >> 5;
    const int wm = warp & 3;     // warp tile: 32 m
    const int wn = warp >> 2;    // warp tile: 64 n
    const uint32_t smem_base = s2u(smem);

    float acc[2][8][4];
#pragma unroll
    for (int mt = 0; mt < 2; mt++)
#pragma unroll
        for (int nt = 0; nt < 8; nt++)
#pragma unroll
            for (int i = 0; i < 4; i++) acc[mt][nt][i] = 0.f;

    const int nk = K / BK;

    auto stage = [&](int kt) {
        const uint32_t so = (uint32_t)(kt & (NSTAGE - 1)) * (STGH * 2);
        const size_t k0 = (size_t)kt * BK;
        // A: 128 rows x 8 chunks(16B) = 1024 chunks, 4/thread
#pragma unroll
        for (int i = 0; i < 4; i++) {
            int idx = tid + i * 256;
            int r = idx >> 3, c8 = idx & 7;
            cpa16(smem_base + so + (uint32_t)(r * PA + c8 * 8) * 2,
                  A + (size_t)(m0 + r) * lda + k0 + c8 * 8);
        }
        if (!BNN) {
            // B: 128 rows x 8 chunks
#pragma unroll
            for (int i = 0; i < 4; i++) {
                int idx = tid + i * 256;
                int r = idx >> 3, c8 = idx & 7;
                cpa16(smem_base + so + ASZ * 2 + (uint32_t)(r * PB + c8 * 8) * 2,
                      B + (size_t)(n0 + r) * ldb + k0 + c8 * 8);
            }
        } else {
            // B: 64 k-rows x 16 chunks
#pragma unroll
            for (int i = 0; i < 4; i++) {
                int idx = tid + i * 256;
                int r = idx >> 4, c8 = idx & 15;
                cpa16(smem_base + so + ASZ * 2 + (uint32_t)(r * PBN + c8 * 8) * 2,
                      B + (size_t)(k0 + r) * ldb + n0 + c8 * 8);
            }
        }
    };

    // lane base offsets (bytes)
    const uint32_t aoff  = smem_base + (uint32_t)(((wm * 32 + (lane & 15)) * PA + (lane >> 4) * 8) * 2);
    const uint32_t btoff = smem_base + ASZ * 2 + (uint32_t)(((wn * 64 + (lane & 15)) * PB + (lane >> 4) * 8) * 2);
    const uint32_t bnoff = smem_base + ASZ * 2 + (uint32_t)(((lane & 15) * PBN + wn * 64 + (lane >> 4) * 8) * 2);

    // prologue
#pragma unroll
    for (int kt = 0; kt < NSTAGE - 1; kt++) {
        stage(kt);
        asm volatile("cp.async.commit_group;");
    }

    for (int kt = 0; kt < nk; kt++) {
        asm volatile("cp.async.wait_group %0;" :: "n"(NSTAGE - 2));
        __syncthreads();

        if (kt + NSTAGE - 1 < nk) stage(kt + NSTAGE - 1);
        asm volatile("cp.async.commit_group;");

        const uint32_t so = (uint32_t)(kt & (NSTAGE - 1)) * (STGH * 2);
#pragma unroll
        for (int ks = 0; ks < 4; ks++) {
            uint32_t a[2][4];
            ldsm4(a[0], aoff + so + ks * 32);
            ldsm4(a[1], aoff + so + 16 * PA * 2 + ks * 32);
            uint32_t bf[8][2];
            if (!BNN) {
#pragma unroll
                for (int nt16 = 0; nt16 < 4; nt16++) {
                    uint32_t t[4];
                    ldsm4(t, btoff + so + nt16 * 16 * PB * 2 + ks * 32);
                    bf[2 * nt16][0] = t[0]; bf[2 * nt16][1] = t[2];
                    bf[2 * nt16 + 1][0] = t[1]; bf[2 * nt16 + 1][1] = t[3];
                }
            } else {
#pragma unroll
                for (int nt16 = 0; nt16 < 4; nt16++) {
                    uint32_t t[4];
                    ldsm4t(t, bnoff + so + ks * (16 * PBN * 2) + nt16 * 32);
                    bf[2 * nt16][0] = t[0]; bf[2 * nt16][1] = t[1];
                    bf[2 * nt16 + 1][0] = t[2]; bf[2 * nt16 + 1][1] = t[3];
                }
            }
#pragma unroll
            for (int mt = 0; mt < 2; mt++)
#pragma unroll
                for (int nt = 0; nt < 8; nt++)
                    mma16816(acc[mt][nt], a[mt], bf[nt]);
        }
        __syncthreads();
    }

    // ---------------- epilogue ----------------
    const int r = lane >> 2;
    const int c = lane & 3;
#pragma unroll
    for (int mt = 0; mt < 2; mt++) {
#pragma unroll
        for (int nt = 0; nt < 8; nt++) {
            float* d = acc[mt][nt];
            const int m1 = m0 + wm * 32 + mt * 16 + r;
            const int m2 = m1 + 8;
            const int nl = n0 + wn * 64 + nt * 8 + 2 * c;

            if (EPI == EPI_BIAS) {
                const float b0v = bias[nl], b1v = bias[nl + 1];
                d[0] += b0v; d[1] += b1v; d[2] += b0v; d[3] += b1v;
            } else if (EPI == EPI_SIG) {
                d[0] = fast_sigmoid(d[0] * scale);
                d[1] = fast_sigmoid(d[1] * scale);
                d[2] = fast_sigmoid(d[2] * scale);
                d[3] = fast_sigmoid(d[3] * scale);
            }

            if (sizeof(OutT) == 2) {
                __half2* Ch = reinterpret_cast<__half2*>(const_cast<OutT*>(C));
                Ch[((size_t)m1 * ldc + nl) >> 1] = __floats2half2_rn(d[0], d[1]);
                Ch[((size_t)m2 * ldc + nl) >> 1] = __floats2half2_rn(d[2], d[3]);
            } else {
                float* Cf = reinterpret_cast<float*>(const_cast<OutT*>(C));
                float2 v01; v01.x = d[0]; v01.y = d[1];
                float2 v23; v23.x = d[2]; v23.y = d[3];
                *reinterpret_cast<float2*>(&Cf[(size_t)m1 * ldc + nl]) = v01;
                *reinterpret_cast<float2*>(&Cf[(size_t)m2 * ldc + nl]) = v23;
            }
        }
    }
}

// ---------------- launcher ----------------
extern "C" void kernel_launch(void* const* d_in, const int* in_sizes, int n_in,
                              void* d_out, int out_size)
{
    (void)in_sizes; (void)n_in; (void)out_size;
    const float* q  = (const float*)d_in[0];
    const float* k  = (const float*)d_in[1];
    const float* v  = (const float*)d_in[2];
    const float* Wq = (const float*)d_in[3];
    const float* bq = (const float*)d_in[4];
    const float* Wk = (const float*)d_in[5];
    const float* bk = (const float*)d_in[6];
    const float* Wv = (const float*)d_in[7];
    const float* bv = (const float*)d_in[8];
    float* out = (float*)d_out;

    __half *hq, *hk, *hv, *hWq, *hWk, *hWv, *qp, *kp, *vp, *z;
    cudaGetSymbolAddress((void**)&hq,  g_hq);
    cudaGetSymbolAddress((void**)&hk,  g_hk);
    cudaGetSymbolAddress((void**)&hv,  g_hv);
    cudaGetSymbolAddress((void**)&hWq, g_hWq);
    cudaGetSymbolAddress((void**)&hWk, g_hWk);
    cudaGetSymbolAddress((void**)&hWv, g_hWv);
    cudaGetSymbolAddress((void**)&qp,  g_qp);
    cudaGetSymbolAddress((void**)&kp,  g_kp);
    cudaGetSymbolAddress((void**)&vp,  g_vp);
    cudaGetSymbolAddress((void**)&z,   g_z);

    cudaFuncSetAttribute(hgemm<EPI_BIAS, false, __half>, cudaFuncAttributeMaxDynamicSharedMemorySize, SMEM_DYN);
    cudaFuncSetAttribute(hgemm<EPI_SIG,  false, __half>, cudaFuncAttributeMaxDynamicSharedMemorySize, SMEM_DYN);
    cudaFuncSetAttribute(hgemm<EPI_NONE, true,  float >, cudaFuncAttributeMaxDynamicSharedMemorySize, SMEM_DYN);

    // one-time streams + events (resource setup only; identical work every call)
    static cudaStream_t s1 = nullptr, s2 = nullptr;
    static cudaEvent_t ev_fork = nullptr, ev_vp = nullptr, ev_k = nullptr;
    static cudaEvent_t ev_z[BATCH] = {nullptr, nullptr, nullptr, nullptr};
    static cudaEvent_t ev_pv = nullptr;
    if (s1 == nullptr) {
        cudaStreamCreateWithFlags(&s1, cudaStreamNonBlocking);
        cudaStreamCreateWithFlags(&s2, cudaStreamNonBlocking);
        cudaEventCreateWithFlags(&ev_fork, cudaEventDisableTiming);
        cudaEventCreateWithFlags(&ev_vp,  cudaEventDisableTiming);
        cudaEventCreateWithFlags(&ev_k,   cudaEventDisableTiming);
        for (int b = 0; b < BATCH; b++)
            cudaEventCreateWithFlags(&ev_z[b], cudaEventDisableTiming);
        cudaEventCreateWithFlags(&ev_pv,  cudaEventDisableTiming);
    }

    const dim3 blk(256);

    // ---- fork ----
    cudaEventRecord(ev_fork, 0);
    cudaStreamWaitEvent(s1, ev_fork, 0);
    cudaStreamWaitEvent(s2, ev_fork, 0);

    // s1: cvt(v, Wv) -> proj vp -> ev_vp
    PPArgs ppv;
    ppv.src[0] = v;  ppv.dst[0] = hv;  ppv.n4[0] = (size_t)MTOT * DIM / 4;
    ppv.src[1] = Wv; ppv.dst[1] = hWv; ppv.n4[1] = (size_t)DIM * DIM / 4;
    cvt_half_k<<<dim3(512, 2), 256, 0, s1>>>(ppv);
    hgemm<EPI_BIAS, false, __half><<<dim3(DIM / BN, MTOT / BM, 1), blk, SMEM_DYN, s1>>>(
        hv, hWv, bv, vp, DIM, DIM, DIM, DIM, 0, 0, 0, 0, 0.f);
    cudaEventRecord(ev_vp, s1);

    // s2: cvt(k, Wk) -> ev_k
    PPArgs ppk;
    ppk.src[0] = k;  ppk.dst[0] = hk;  ppk.n4[0] = (size_t)MTOT * DIM / 4;
    ppk.src[1] = Wk; ppk.dst[1] = hWk; ppk.n4[1] = (size_t)QKD * DIM / 4;
    cvt_half_k<<<dim3(512, 2), 256, 0, s2>>>(ppk);
    cudaEventRecord(ev_k, s2);

    // main: cvt(q, Wq)
    PPArgs ppq;
    ppq.src[0] = q;  ppq.dst[0] = hq;  ppq.n4[0] = (size_t)MTOT * DIM / 4;
    ppq.src[1] = Wq; ppq.dst[1] = hWq; ppq.n4[1] = (size_t)QKD * DIM / 4;
    cvt_half_k<<<dim3(512, 2), 256>>>(ppq);

    // main: qp+kp merged (needs hk/hWk from s2)
    cudaStreamWaitEvent(0, ev_k, 0);
    hgemm<EPI_BIAS, false, __half><<<dim3(QKD / BN, MTOT / BM, 2), blk, SMEM_DYN>>>(
        hq, hWq, bq, qp, DIM, DIM, DIM, QKD,
        (size_t)(hk - hq), (size_t)(hWk - hWq), (size_t)(kp - qp), (size_t)(bk - bq), 0.f);

    // s1 already has vp done-ordering; PV launches go on s1 after per-batch z events
    for (int b = 0; b < BATCH; b++) {
        // main: z[b] = sigmoid(qp[b] @ kp[b]^T / 16)   [4096,4096]
        hgemm<EPI_SIG, false, __half><<<dim3(SEQ / BN, SEQ / BM, 1), blk, SMEM_DYN>>>(
            qp + (size_t)b * SEQ * QKD, kp + (size_t)b * SEQ * QKD, nullptr,
            z + (size_t)b * SEQ * SEQ, QKD, QKD, QKD, SEQ, 0, 0, 0, 0, 1.f / 16.f);
        cudaEventRecord(ev_z[b], 0);

        // s1: PV[b] = z[b] @ vp[b]   [4096,1024] fp32
        cudaStreamWaitEvent(s1, ev_z[b], 0);
        hgemm<EPI_NONE, true, float><<<dim3(DIM / BN, SEQ / BM, 1), blk, SMEM_DYN, s1>>>(
            z + (size_t)b * SEQ * SEQ, vp + (size_t)b * SEQ * DIM, nullptr,
            out + (size_t)b * SEQ * DIM, SEQ, SEQ, DIM, DIM, 0, 0, 0, 0, 0.f);
    }
    cudaEventRecord(ev_pv, s1);

    // ---- join: graph output complete on main stream ----
    cudaStreamWaitEvent(0, ev_pv, 0);
}

// round 14
// speedup vs baseline: 1.0338x; 1.0338x over previous
#include <cuda_runtime.h>
#include <cuda_fp16.h>
#include <cstddef>
#include <cstdint>

#define BATCH 4
#define SEQ   4096
#define DIM   1024
#define QKD   256
#define MTOT  16384

// CTA 128x128, warp tile 32x64, 8 warps, BK=64, 2 stages
#define BM 128
#define BN 128
#define BK 64
#define NSTAGE 2
#define PA  72     // A smem pitch (halfs), 144B rows -> conflict-free ldmatrix
#define PB  72     // B TN pitch
#define PBN 136    // B NN pitch (64 rows x 128 cols)
#define ASZ (BM*PA)            // 9216 halfs
#define BSZ (BM*PB)            // 9216 halfs (>= 64*136 = 8704)
#define STGH (ASZ+BSZ)         // halfs per stage
#define SMEM_DYN (NSTAGE*STGH*2)   // 73728 B

// ---------------- scratch (bss device globals; allocation-free) ----------------
__device__ __half g_hq [(size_t)MTOT*DIM];
__device__ __half g_hk [(size_t)MTOT*DIM];
__device__ __half g_hv [(size_t)MTOT*DIM];
__device__ __half g_hWq[(size_t)QKD*DIM];
__device__ __half g_hWk[(size_t)QKD*DIM];
__device__ __half g_hWv[(size_t)DIM*DIM];
__device__ __half g_qp [(size_t)MTOT*QKD];
__device__ __half g_kp [(size_t)MTOT*QKD];
__device__ __half g_vp [(size_t)MTOT*DIM];
__device__ __half g_z  [(size_t)BATCH*SEQ*SEQ];

// ---------------- helpers ----------------
__device__ __forceinline__ uint32_t s2u(const void* p) {
    return (uint32_t)__cvta_generic_to_shared(p);
}
__device__ __forceinline__ void cpa16(uint32_t dst, const void* src) {
    asm volatile("cp.async.cg.shared.global [%0], [%1], 16;" :: "r"(dst), "l"(src));
}
__device__ __forceinline__ void ldsm4(uint32_t* r, uint32_t a) {
    asm volatile("ldmatrix.sync.aligned.m8n8.x4.shared.b16 {%0,%1,%2,%3}, [%4];"
        : "=r"(r[0]), "=r"(r[1]), "=r"(r[2]), "=r"(r[3]) : "r"(a));
}
__device__ __forceinline__ void ldsm4t(uint32_t* r, uint32_t a) {
    asm volatile("ldmatrix.sync.aligned.m8n8.x4.trans.shared.b16 {%0,%1,%2,%3}, [%4];"
        : "=r"(r[0]), "=r"(r[1]), "=r"(r[2]), "=r"(r[3]) : "r"(a));
}
__device__ __forceinline__ void mma16816(float* d, const uint32_t* a, const uint32_t* b) {
    asm volatile(
        "mma.sync.aligned.m16n8k16.row.col.f32.f16.f16.f32 "
        "{%0,%1,%2,%3}, {%4,%5,%6,%7}, {%8,%9}, {%0,%1,%2,%3};"
        : "+f"(d[0]), "+f"(d[1]), "+f"(d[2]), "+f"(d[3])
        : "r"(a[0]), "r"(a[1]), "r"(a[2]), "r"(a[3]), "r"(b[0]), "r"(b[1]));
}
// sigmoid(x) = 0.5*tanh(0.5*x) + 0.5  via HW MUFU.TANH (1 MUFU, no divide)
__device__ __forceinline__ float fast_sigmoid(float x) {
    float t;
    asm("tanh.approx.f32 %0, %1;" : "=f"(t) : "f"(x * 0.5f));
    return fmaf(t, 0.5f, 0.5f);
}

// ---------------- fp32 -> fp16 convert (grid.y selects segment) ----------------
struct PPArgs {
    const float* src[2];
    __half* dst[2];
    size_t n4[2];
};
__global__ void cvt_half_k(PPArgs pp) {
    const int seg = blockIdx.y;
    const float* in = pp.src[seg];
    __half2* out = reinterpret_cast<__half2*>(pp.dst[seg]);
    const size_t n4 = pp.n4[seg];
    size_t i = (size_t)blockIdx.x * blockDim.x + threadIdx.x;
    const size_t stride = (size_t)gridDim.x * blockDim.x;
    for (; i < n4; i += stride) {
        float4 v = reinterpret_cast<const float4*>(in)[i];
        out[2 * i]     = __floats2half2_rn(v.x, v.y);
        out[2 * i + 1] = __floats2half2_rn(v.z, v.w);
    }
}

// ---------------- fp16 tensor-core GEMM ----------------
// C[m][n] = sum_k A[m][k] * B_frag(n,k); blockIdx.z batches via element strides
//   BNN=false: B gmem is [N][K] (K-contig)  -> ldmatrix non-trans
//   BNN=true : B gmem is [K][N] (N-contig)  -> ldmatrix.trans
#define EPI_BIAS 0
#define EPI_SIG  1
#define EPI_NONE 2

template<int EPI, bool BNN, typename OutT>
__global__ __launch_bounds__(256, 2)
void hgemm(const __half* __restrict__ A, const __half* __restrict__ B,
           const float* __restrict__ bias, OutT* __restrict__ C,
           int K, size_t lda, size_t ldb, size_t ldc,
           size_t sA, size_t sB, size_t sC, size_t sBias, float scale)
{
    extern __shared__ __align__(128) __half smem[];

    const int b = blockIdx.z;
    A += (size_t)b * sA;  B += (size_t)b * sB;  C += (size_t)b * sC;
    if (EPI == EPI_BIAS) bias += (size_t)b * sBias;
    const int m0 = blockIdx.y * BM;
    const int n0 = blockIdx.x * BN;
    const int tid  = threadIdx.x;
    const int lane = tid & 31;
    const int warp = tid >> 5;
    const int wm = warp & 3;     // warp tile: 32 m
    const int wn = warp >> 2;    // warp tile: 64 n
    const uint32_t smem_base = s2u(smem);

    float acc[2][8][4];
#pragma unroll
    for (int mt = 0; mt < 2; mt++)
#pragma unroll
        for (int nt = 0; nt < 8; nt++)
#pragma unroll
            for (int i = 0; i < 4; i++) acc[mt][nt][i] = 0.f;

    const int nk = K / BK;

    auto stage = [&](int kt) {
        const uint32_t so = (uint32_t)(kt & (NSTAGE - 1)) * (STGH * 2);
        const size_t k0 = (size_t)kt * BK;
        // A: 128 rows x 8 chunks(16B) = 1024 chunks, 4/thread
#pragma unroll
        for (int i = 0; i < 4; i++) {
            int idx = tid + i * 256;
            int r = idx >> 3, c8 = idx & 7;
            cpa16(smem_base + so + (uint32_t)(r * PA + c8 * 8) * 2,
                  A + (size_t)(m0 + r) * lda + k0 + c8 * 8);
        }
        if (!BNN) {
            // B: 128 rows x 8 chunks
#pragma unroll
            for (int i = 0; i < 4; i++) {
                int idx = tid + i * 256;
                int r = idx >> 3, c8 = idx & 7;
                cpa16(smem_base + so + ASZ * 2 + (uint32_t)(r * PB + c8 * 8) * 2,
                      B + (size_t)(n0 + r) * ldb + k0 + c8 * 8);
            }
        } else {
            // B: 64 k-rows x 16 chunks
#pragma unroll
            for (int i = 0; i < 4; i++) {
                int idx = tid + i * 256;
                int r = idx >> 4, c8 = idx & 15;
                cpa16(smem_base + so + ASZ * 2 + (uint32_t)(r * PBN + c8 * 8) * 2,
                      B + (size_t)(k0 + r) * ldb + n0 + c8 * 8);
            }
        }
    };

    // lane base offsets (bytes)
    const uint32_t aoff  = smem_base + (uint32_t)(((wm * 32 + (lane & 15)) * PA + (lane >> 4) * 8) * 2);
    const uint32_t btoff = smem_base + ASZ * 2 + (uint32_t)(((wn * 64 + (lane & 15)) * PB + (lane >> 4) * 8) * 2);
    const uint32_t bnoff = smem_base + ASZ * 2 + (uint32_t)(((lane & 15) * PBN + wn * 64 + (lane >> 4) * 8) * 2);

    // prologue
#pragma unroll
    for (int kt = 0; kt < NSTAGE - 1; kt++) {
        stage(kt);
        asm volatile("cp.async.commit_group;");
    }

    for (int kt = 0; kt < nk; kt++) {
        asm volatile("cp.async.wait_group %0;" :: "n"(NSTAGE - 2));
        __syncthreads();

        if (kt + NSTAGE - 1 < nk) stage(kt + NSTAGE - 1);
        asm volatile("cp.async.commit_group;");

        const uint32_t so = (uint32_t)(kt & (NSTAGE - 1)) * (STGH * 2);
#pragma unroll
        for (int ks = 0; ks < 4; ks++) {
            uint32_t a[2][4];
            ldsm4(a[0], aoff + so + ks * 32);
            ldsm4(a[1], aoff + so + 16 * PA * 2 + ks * 32);
            uint32_t bf[8][2];
            if (!BNN) {
#pragma unroll
                for (int nt16 = 0; nt16 < 4; nt16++) {
                    uint32_t t[4];
                    ldsm4(t, btoff + so + nt16 * 16 * PB * 2 + ks * 32);
                    bf[2 * nt16][0] = t[0]; bf[2 * nt16][1] = t[2];
                    bf[2 * nt16 + 1][0] = t[1]; bf[2 * nt16 + 1][1] = t[3];
                }
            } else {
#pragma unroll
                for (int nt16 = 0; nt16 < 4; nt16++) {
                    uint32_t t[4];
                    ldsm4t(t, bnoff + so + ks * (16 * PBN * 2) + nt16 * 32);
                    bf[2 * nt16][0] = t[0]; bf[2 * nt16][1] = t[1];
                    bf[2 * nt16 + 1][0] = t[2]; bf[2 * nt16 + 1][1] = t[3];
                }
            }
#pragma unroll
            for (int mt = 0; mt < 2; mt++)
#pragma unroll
                for (int nt = 0; nt < 8; nt++)
                    mma16816(acc[mt][nt], a[mt], bf[nt]);
        }
        __syncthreads();
    }

    // ---------------- epilogue ----------------
    const int r = lane >> 2;
    const int c = lane & 3;
#pragma unroll
    for (int mt = 0; mt < 2; mt++) {
#pragma unroll
        for (int nt = 0; nt < 8; nt++) {
            float* d = acc[mt][nt];
            const int m1 = m0 + wm * 32 + mt * 16 + r;
            const int m2 = m1 + 8;
            const int nl = n0 + wn * 64 + nt * 8 + 2 * c;

            if (EPI == EPI_BIAS) {
                const float b0v = bias[nl], b1v = bias[nl + 1];
                d[0] += b0v; d[1] += b1v; d[2] += b0v; d[3] += b1v;
            } else if (EPI == EPI_SIG) {
                d[0] = fast_sigmoid(d[0] * scale);
                d[1] = fast_sigmoid(d[1] * scale);
                d[2] = fast_sigmoid(d[2] * scale);
                d[3] = fast_sigmoid(d[3] * scale);
            }

            if (sizeof(OutT) == 2) {
                __half2* Ch = reinterpret_cast<__half2*>(const_cast<OutT*>(C));
                Ch[((size_t)m1 * ldc + nl) >> 1] = __floats2half2_rn(d[0], d[1]);
                Ch[((size_t)m2 * ldc + nl) >> 1] = __floats2half2_rn(d[2], d[3]);
            } else {
                float* Cf = reinterpret_cast<float*>(const_cast<OutT*>(C));
                float2 v01; v01.x = d[0]; v01.y = d[1];
                float2 v23; v23.x = d[2]; v23.y = d[3];
                *reinterpret_cast<float2*>(&Cf[(size_t)m1 * ldc + nl]) = v01;
                *reinterpret_cast<float2*>(&Cf[(size_t)m2 * ldc + nl]) = v23;
            }
        }
    }
}

// ---------------- launcher ----------------
extern "C" void kernel_launch(void* const* d_in, const int* in_sizes, int n_in,
                              void* d_out, int out_size)
{
    (void)in_sizes; (void)n_in; (void)out_size;
    const float* q  = (const float*)d_in[0];
    const float* k  = (const float*)d_in[1];
    const float* v  = (const float*)d_in[2];
    const float* Wq = (const float*)d_in[3];
    const float* bq = (const float*)d_in[4];
    const float* Wk = (const float*)d_in[5];
    const float* bk = (const float*)d_in[6];
    const float* Wv = (const float*)d_in[7];
    const float* bv = (const float*)d_in[8];
    float* out = (float*)d_out;

    __half *hq, *hk, *hv, *hWq, *hWk, *hWv, *qp, *kp, *vp, *z;
    cudaGetSymbolAddress((void**)&hq,  g_hq);
    cudaGetSymbolAddress((void**)&hk,  g_hk);
    cudaGetSymbolAddress((void**)&hv,  g_hv);
    cudaGetSymbolAddress((void**)&hWq, g_hWq);
    cudaGetSymbolAddress((void**)&hWk, g_hWk);
    cudaGetSymbolAddress((void**)&hWv, g_hWv);
    cudaGetSymbolAddress((void**)&qp,  g_qp);
    cudaGetSymbolAddress((void**)&kp,  g_kp);
    cudaGetSymbolAddress((void**)&vp,  g_vp);
    cudaGetSymbolAddress((void**)&z,   g_z);

    cudaFuncSetAttribute(hgemm<EPI_BIAS, false, __half>, cudaFuncAttributeMaxDynamicSharedMemorySize, SMEM_DYN);
    cudaFuncSetAttribute(hgemm<EPI_SIG,  false, __half>, cudaFuncAttributeMaxDynamicSharedMemorySize, SMEM_DYN);
    cudaFuncSetAttribute(hgemm<EPI_NONE, true,  float >, cudaFuncAttributeMaxDynamicSharedMemorySize, SMEM_DYN);

    // one-time streams + events (resource setup only; identical work every call)
    static cudaStream_t s1 = nullptr, s2 = nullptr;
    static cudaEvent_t ev_fork = nullptr, ev_vp = nullptr, ev_kp = nullptr;
    if (s1 == nullptr) {
        cudaStreamCreateWithFlags(&s1, cudaStreamNonBlocking);
        cudaStreamCreateWithFlags(&s2, cudaStreamNonBlocking);
        cudaEventCreateWithFlags(&ev_fork, cudaEventDisableTiming);
        cudaEventCreateWithFlags(&ev_vp,  cudaEventDisableTiming);
        cudaEventCreateWithFlags(&ev_kp,  cudaEventDisableTiming);
    }

    const dim3 blk(256);

    // ---- fork ----
    cudaEventRecord(ev_fork, 0);
    cudaStreamWaitEvent(s1, ev_fork, 0);
    cudaStreamWaitEvent(s2, ev_fork, 0);

    // s1: cvt(v, Wv) -> proj vp -> ev_vp
    PPArgs ppv;
    ppv.src[0] = v;  ppv.dst[0] = hv;  ppv.n4[0] = (size_t)MTOT * DIM / 4;
    ppv.src[1] = Wv; ppv.dst[1] = hWv; ppv.n4[1] = (size_t)DIM * DIM / 4;
    cvt_half_k<<<dim3(512, 2), 256, 0, s1>>>(ppv);
    hgemm<EPI_BIAS, false, __half><<<dim3(DIM / BN, MTOT / BM, 1), blk, SMEM_DYN, s1>>>(
        hv, hWv, bv, vp, DIM, DIM, DIM, DIM, 0, 0, 0, 0, 0.f);
    cudaEventRecord(ev_vp, s1);

    // s2: cvt(k, Wk) -> proj kp -> ev_kp
    PPArgs ppk;
    ppk.src[0] = k;  ppk.dst[0] = hk;  ppk.n4[0] = (size_t)MTOT * DIM / 4;
    ppk.src[1] = Wk; ppk.dst[1] = hWk; ppk.n4[1] = (size_t)QKD * DIM / 4;
    cvt_half_k<<<dim3(512, 2), 256, 0, s2>>>(ppk);
    hgemm<EPI_BIAS, false, __half><<<dim3(QKD / BN, MTOT / BM, 1), blk, SMEM_DYN, s2>>>(
        hk, hWk, bk, kp, DIM, DIM, DIM, QKD, 0, 0, 0, 0, 0.f);
    cudaEventRecord(ev_kp, s2);

    // main: cvt(q, Wq) -> proj qp
    PPArgs ppq;
    ppq.src[0] = q;  ppq.dst[0] = hq;  ppq.n4[0] = (size_t)MTOT * DIM / 4;
    ppq.src[1] = Wq; ppq.dst[1] = hWq; ppq.n4[1] = (size_t)QKD * DIM / 4;
    cvt_half_k<<<dim3(512, 2), 256>>>(ppq);
    hgemm<EPI_BIAS, false, __half><<<dim3(QKD / BN, MTOT / BM, 1), blk, SMEM_DYN>>>(
        hq, hWq, bq, qp, DIM, DIM, DIM, QKD, 0, 0, 0, 0, 0.f);

    // main: z = sigmoid(qp @ kp^T / 16)  per batch [4096,4096]  (needs kp)
    cudaStreamWaitEvent(0, ev_kp, 0);
    hgemm<EPI_SIG, false, __half><<<dim3(SEQ / BN, SEQ / BM, BATCH), blk, SMEM_DYN>>>(
        qp, kp, nullptr, z, QKD, QKD, QKD, SEQ,
        (size_t)SEQ * QKD, (size_t)SEQ * QKD, (size_t)SEQ * SEQ, 0, 1.f / 16.f);

    // ---- join: PV needs vp ----
    cudaStreamWaitEvent(0, ev_vp, 0);

    // main: out = z @ vp  per batch [4096,1024] fp32 (NN: vp is [k][n])
    hgemm<EPI_NONE, true, float><<<dim3(DIM / BN, SEQ / BM, BATCH), blk, SMEM_DYN>>>(
        z, vp, nullptr, out, SEQ, SEQ, DIM, DIM,
        (size_t)SEQ * SEQ, (size_t)SEQ * DIM, (size_t)SEQ * DIM, 0, 0.f);
}